// round 5
// baseline (speedup 1.0000x reference)
#include <cuda_runtime.h>
#include <math.h>
#include <stdint.h>

// Shapes fixed by the problem definition.
#define Bv 4
#define Tv 2048
#define Dv 384
#define Hv 192
#define VD (Dv/4)          // 96 float4 per row
#define MR 16              // MLP rows per block (8 warps x 2 rows)
#define NB0 (Tv/MR)        // 128 batch-0 MLP blocks
#define NB13 ((Bv-1)*Tv/MR)// 384 MLP blocks for batches 1..3
#define KC 8               // w1 k-tile rows (double buffered)
#define NTILE (Dv/KC)      // 48
#define GMIN (8*Tv)        // guaranteed minimum total length (MIN_DUR=8)
#define NTHR 256
#define SMEMB ((MR*Dv + 2*KC*Hv)*4)   // 36864 bytes

// Scratch (no allocs allowed).
__device__ float g_dur[Tv];
__device__ int   g_cum[Tv];
__device__ int   g_total;
__device__ int   g_cnt;     // batch-0 completion counter (self-resetting)

#define FMA_F32X2(d, a, b, c) \
    asm("fma.rn.f32x2 %0, %1, %2, %3;" : "=l"(d) : "l"(a), "l"(b), "l"(c))
#define PACK_DUP(out, v) \
    asm("mov.b64 %0, {%1, %1};" : "=l"(out) : "r"(v))
#define UNPACK2(lo, hi, in) \
    asm("mov.b64 {%0, %1}, %2;" : "=r"(lo), "=r"(hi) : "l"(in))

#define CP16(dst_u32, src_ptr) \
    asm volatile("cp.async.cg.shared.global [%0], [%1], 16;\n" :: "r"(dst_u32), "l"(src_ptr))
#define CP_COMMIT() asm volatile("cp.async.commit_group;\n")
#define CP_WAIT(n)  asm volatile("cp.async.wait_group %0;\n" :: "n"(n))

__device__ __forceinline__ uint32_t smem_u32(const void* p) {
    return (uint32_t)__cvta_generic_to_shared(p);
}

__device__ __forceinline__ float duration_of(float z) {
    // softplus -> clamp to MIN_DUR=8 -> round (nearest-even, matching jnp.round)
    float sp = (z > 20.f) ? z : log1pf(expf(z));
    return rintf(fmaxf(sp, 8.f));
}

// MLP for MR=16 rows at row0 (8 warps x 2 rows, 3 j-pairs per lane).
// w1 streamed via cp.async double-buffered KC=8 tiles; x tile loaded once.
// Packed fma.rn.f32x2 accumulation. Writes g_dur for rows < Tv and the
// duration_pred output tail (if present).
__device__ __forceinline__ void mlp_rows(
    const float* __restrict__ x, const float* __restrict__ w1,
    const float* __restrict__ b1, const float* __restrict__ w2,
    const float* __restrict__ b2, int row0,
    float* smem, float* __restrict__ out_tail)
{
    float* s_x = smem;                 // [MR][Dv]    24KB
    float* s_w = smem + MR * Dv;       // [2][KC][Hv] 12KB

    const int tid  = threadIdx.x;
    const int lane = tid & 31;
    const int warp = tid >> 5;
    const int r0 = warp * 2, r1 = r0 + 1;

    // Async-load x tile (once): 1536 float4.
    {
        const float4* __restrict__ xg = (const float4*)(x + (long)row0 * Dv);
        uint32_t sx = smem_u32(s_x);
#pragma unroll
        for (int i = tid; i < MR * Dv / 4; i += NTHR)
            CP16(sx + (uint32_t)i * 16u, xg + i);
        CP_COMMIT();
    }
    // Prefetch w tile 0 (384 float4).
    {
        const float4* __restrict__ wg = (const float4*)w1;
        uint32_t sw = smem_u32(s_w);
        for (int i = tid; i < KC * Hv / 4; i += NTHR)
            CP16(sw + (uint32_t)i * 16u, wg + i);
        CP_COMMIT();
    }

    uint64_t acc0[3] = {0ull, 0ull, 0ull};
    uint64_t acc1[3] = {0ull, 0ull, 0ull};

    for (int t = 0; t < NTILE; ++t) {
        if (t + 1 < NTILE) {
            const float4* __restrict__ wg =
                (const float4*)(w1 + (long)(t + 1) * KC * Hv);
            uint32_t sw = smem_u32(s_w + ((t + 1) & 1) * KC * Hv);
            for (int i = tid; i < KC * Hv / 4; i += NTHR)
                CP16(sw + (uint32_t)i * 16u, wg + i);
            CP_COMMIT();
            CP_WAIT(1);
        } else {
            CP_WAIT(0);
        }
        __syncthreads();

        const float* wb  = s_w + (t & 1) * KC * Hv;
        const float* x0p = s_x + r0 * Dv + t * KC;
        const float* x1p = x0p + Dv;
#pragma unroll
        for (int k0 = 0; k0 < KC; k0 += 4) {
            float4 xa0 = *(const float4*)(x0p + k0);
            float4 xa1 = *(const float4*)(x1p + k0);
#pragma unroll
            for (int kk = 0; kk < 4; ++kk) {
                uint64_t xd0, xd1;
                PACK_DUP(xd0, __float_as_uint((&xa0.x)[kk]));
                PACK_DUP(xd1, __float_as_uint((&xa1.x)[kk]));
#pragma unroll
                for (int m = 0; m < 3; ++m) {
                    uint64_t wv = *(const uint64_t*)(wb + (k0 + kk) * Hv
                                                     + 2 * (lane + 32 * m));
                    FMA_F32X2(acc0[m], xd0, wv, acc0[m]);
                    FMA_F32X2(acc1[m], xd1, wv, acc1[m]);
                }
            }
        }
        __syncthreads();
    }

    // Epilogue: bias, relu, dot with w2, warp-reduce per row.
    float bz = b2[0];
    float p0 = 0.f, p1 = 0.f;
#pragma unroll
    for (int m = 0; m < 3; ++m) {
        int jp = lane + 32 * m;
        float2 bb = *(const float2*)(b1 + 2 * jp);
        float2 ww = *(const float2*)(w2 + 2 * jp);
        uint32_t lo, hi;
        UNPACK2(lo, hi, acc0[m]);
        p0 += fmaxf(__uint_as_float(lo) + bb.x, 0.f) * ww.x
            + fmaxf(__uint_as_float(hi) + bb.y, 0.f) * ww.y;
        UNPACK2(lo, hi, acc1[m]);
        p1 += fmaxf(__uint_as_float(lo) + bb.x, 0.f) * ww.x
            + fmaxf(__uint_as_float(hi) + bb.y, 0.f) * ww.y;
    }
#pragma unroll
    for (int off = 16; off > 0; off >>= 1) {
        p0 += __shfl_xor_sync(0xffffffffu, p0, off);
        p1 += __shfl_xor_sync(0xffffffffu, p1, off);
    }
    if (lane == 0) {
        float d0 = duration_of(p0 + bz);
        float d1 = duration_of(p1 + bz);
        int a = row0 + r0, b = row0 + r1;
        if (out_tail) { out_tail[a] = d0; out_tail[b] = d1; }
        if (a < Tv) g_dur[a] = d0;
        if (b < Tv) g_dur[b] = d1;
    }
}

// K1: blocks [0,NB0) run the batch-0 MLP; the last finisher (atomic counter)
// also runs the cumsum scan inline. Remaining blocks zero-fill the FINAL
// 'ztail' positions of each output slab (overwritten later by the copy kernel
// if g_total ever reached that far — stream order makes that correct).
__global__ __launch_bounds__(NTHR)
void k1_kernel(const float* __restrict__ x, const float* __restrict__ w1,
               const float* __restrict__ b1, const float* __restrict__ w2,
               const float* __restrict__ b2, float* __restrict__ out,
               long TL, long tail_off, long zT0, int z1c)
{
    extern __shared__ float smem[];
    const int tid  = threadIdx.x;
    const int lane = tid & 31;
    const int warp = tid >> 5;

    if ((int)blockIdx.x < NB0) {
        mlp_rows(x, w1, b1, w2, b2, (int)blockIdx.x * MR, smem,
                 tail_off >= 0 ? out + tail_off : nullptr);
        __shared__ int s_go;
        __syncthreads();
        if (tid == 0) {
            __threadfence();
            s_go = (atomicAdd(&g_cnt, 1) == NB0 - 1);
        }
        __syncthreads();
        if (!s_go) return;
        __threadfence();
        // Inclusive scan of (int)g_dur -> g_cum, g_total (256 thr x 8).
        int* s_sum = (int*)smem;
        int loc[8]; int s = 0;
#pragma unroll
        for (int i = 0; i < 8; ++i) { loc[i] = (int)g_dur[tid * 8 + i]; s += loc[i]; }
        s_sum[tid] = s;
        __syncthreads();
#pragma unroll
        for (int off = 1; off < 256; off <<= 1) {
            int v = (tid >= off) ? s_sum[tid - off] : 0;
            __syncthreads();
            s_sum[tid] += v;
            __syncthreads();
        }
        int run = (tid > 0) ? s_sum[tid - 1] : 0;
#pragma unroll
        for (int i = 0; i < 8; ++i) { run += loc[i]; g_cum[tid * 8 + i] = run; }
        if (tid == 255) { g_total = run; g_cnt = 0; }   // reset for next replay
        return;
    }

    // Tail zero-fill: 16 positions per block, warp -> 2 positions, lane -> 3 f4.
    if (z1c == 0) return;
    int z = (int)blockIdx.x - NB0;
    int b = z / z1c, c = z % z1c;
    long p0 = zT0 + (long)c * 16;
    float4* __restrict__ out4 = (float4*)out;
    const float4 zf = make_float4(0.f, 0.f, 0.f, 0.f);
#pragma unroll
    for (int s2 = 0; s2 < 2; ++s2) {
        long p = p0 + warp * 2 + s2;
        if (p >= TL) continue;
        float4* d = out4 + ((long)b * TL + p) * VD + lane;
        __stcs(d, zf); __stcs(d + 32, zf); __stcs(d + 64, zf);
    }
}

// K3: one grid, three roles (all independent given K1's scan):
//  [0, mlpN)            MLP for batches 1..3 (duration_pred tail only)
//  [mlpN, mlpN+cpB)     gather-copy for p < g_total (chunk-major, 16 pos/block)
//  [mlpN+cpB, ...)      zero-fill [zstart, zT0) skipping p < g_total
__global__ __launch_bounds__(NTHR)
void k3_kernel(const float* __restrict__ x, const float* __restrict__ w1,
               const float* __restrict__ b1, const float* __restrict__ w2,
               const float* __restrict__ b2, float* __restrict__ out,
               long TL, long tail_off, long zstart, long zT0,
               int mlpN, int cpB)
{
    extern __shared__ float smem[];
    const int tid  = threadIdx.x;
    const int lane = tid & 31;
    const int warp = tid >> 5;
    int bid = (int)blockIdx.x;

    if (bid < mlpN) {
        mlp_rows(x, w1, b1, w2, b2, Tv + bid * MR, smem, out + tail_off);
        return;
    }
    bid -= mlpN;
    float4* __restrict__ out4 = (float4*)out;

    if (bid < cpB) {
        int b  = bid & 3;
        long p0 = (long)(bid >> 2) * 16;
        int total = g_total;
        if (p0 >= (long)total) return;

        __shared__ int s_idx[16];
        __shared__ int s_ok[16];
        if (tid < 16) {
            long p = p0 + tid;
            // searchsorted(cum, p, side="right") == upper_bound
            int lo = 0, hi = Tv;
            while (lo < hi) {
                int mid = (lo + hi) >> 1;
                if ((long)g_cum[mid] <= p) lo = mid + 1; else hi = mid;
            }
            s_idx[tid] = (lo < Tv) ? lo : (Tv - 1);
            s_ok[tid]  = (p < (long)total) && (p < TL);
        }
        __syncthreads();

        const float4* __restrict__ x4 = (const float4*)x;
#pragma unroll
        for (int s2 = 0; s2 < 2; ++s2) {
            int pl = warp * 2 + s2;
            if (!s_ok[pl]) continue;
            long p = p0 + pl;
            const float4* src = x4 + ((long)b * Tv + s_idx[pl]) * VD + lane;
            float4* dst = out4 + ((long)b * TL + p) * VD + lane;
#pragma unroll
            for (int k2 = 0; k2 < 3; ++k2)
                __stcs(dst + 32 * k2, __ldg(src + 32 * k2));
        }
        return;
    }
    bid -= cpB;

    // Mid-region zero-fill: 32 positions per block, warp -> 4, lane -> 3 f4.
    int b  = bid & 3;
    long pb = zstart + (long)(bid >> 2) * 32;
    int total = g_total;
    const float4 zf = make_float4(0.f, 0.f, 0.f, 0.f);
#pragma unroll
    for (int s2 = 0; s2 < 4; ++s2) {
        long p = pb + warp * 4 + s2;
        if (p >= zT0 || p < (long)total) continue;
        float4* d = out4 + ((long)b * TL + p) * VD + lane;
        __stcs(d, zf); __stcs(d + 32, zf); __stcs(d + 64, zf);
    }
}

extern "C" void kernel_launch(void* const* d_in, const int* in_sizes, int n_in,
                              void* d_out, int out_size)
{
    const float* x  = (const float*)d_in[0];
    const float* w1 = (const float*)d_in[1];
    const float* b1 = (const float*)d_in[2];
    const float* w2 = (const float*)d_in[3];
    const float* b2 = (const float*)d_in[4];
    float* out = (float*)d_out;

    // Output layout: expanded (Bv, TL, Dv) then duration_pred (Bv, Tv).
    long osz = (long)out_size;
    long TL, tail_off;
    if (osz % ((long)Bv * Dv) == 0) {          // no duration tail in output
        TL = osz / ((long)Bv * Dv);
        tail_off = -1;
    } else {
        TL = (osz - (long)Bv * Tv) / ((long)Bv * Dv);
        tail_off = (long)Bv * TL * Dv;
    }

    long zstart = (long)GMIN < TL ? (long)GMIN : TL;  // zeros only for p >= zstart
    long ztail  = TL - zstart; if (ztail > 1024) ztail = 1024;  // K1's share
    long zT0    = TL - ztail;
    int  z1c    = (int)((ztail + 15) / 16);           // K1 zero chunks per slab

    int cp_chunks = (int)((TL + 15) / 16);
    int cpB   = Bv * cp_chunks;
    long zlen3 = zT0 - zstart; if (zlen3 < 0) zlen3 = 0;
    int z3B   = Bv * (int)((zlen3 + 31) / 32);
    int mlpN  = (tail_off >= 0) ? NB13 : 0;

    k1_kernel<<<NB0 + Bv * z1c, NTHR, SMEMB>>>(x, w1, b1, w2, b2, out,
                                               TL, tail_off, zT0, z1c);
    k3_kernel<<<mlpN + cpB + z3B, NTHR, SMEMB>>>(x, w1, b1, w2, b2, out,
                                                 TL, tail_off, zstart, zT0,
                                                 mlpN, cpB);
}

// round 6
// speedup vs baseline: 1.4568x; 1.4568x over previous
#include <cuda_runtime.h>
#include <math.h>
#include <stdint.h>

// Shapes fixed by the problem definition.
#define Bv 4
#define Tv 2048
#define Dv 384
#define Hv 192
#define VD (Dv/4)     // 96 float4 per row
#define MROWS 32      // rows per MLP block (8 warps x 4 rows)
#define NB_MLP (Bv*Tv/MROWS)   // 256 MLP blocks cover all batches
#define KC 16         // k-tile rows (double buffered)
#define NTILE (Dv/KC) // 24
#define GMIN (8*Tv)   // guaranteed minimum total length (MIN_DUR=8)
#define CPP 32        // output positions per copy block
#define ZPB 6144      // float4 per zero block (256 thr x 24)
#define NTHR 256

// Scratch (no allocs allowed): batch-0 durations, their cumsum, total.
__device__ float g_dur[Tv];
__device__ int   g_cum[Tv];
__device__ int   g_total;

#define FMA_F32X2(d, a, b, c) \
    asm("fma.rn.f32x2 %0, %1, %2, %3;" : "=l"(d) : "l"(a), "l"(b), "l"(c))
#define PACK_DUP(out, v) \
    asm("mov.b64 %0, {%1, %1};" : "=l"(out) : "r"(v))
#define UNPACK2(lo, hi, in) \
    asm("mov.b64 {%0, %1}, %2;" : "=r"(lo), "=r"(hi) : "l"(in))

#define CP16(dst_u32, src_ptr) \
    asm volatile("cp.async.cg.shared.global [%0], [%1], 16;\n" :: "r"(dst_u32), "l"(src_ptr))
#define CP_COMMIT() asm volatile("cp.async.commit_group;\n")
#define CP_WAIT(n)  asm volatile("cp.async.wait_group %0;\n" :: "n"(n))

__device__ __forceinline__ uint32_t smem_u32(const void* p) {
    return (uint32_t)__cvta_generic_to_shared(p);
}

__device__ __forceinline__ float duration_of(float z) {
    // softplus -> clamp to MIN_DUR=8 -> round (nearest-even, matching jnp.round)
    float sp = (z > 20.f) ? z : log1pf(expf(z));
    return rintf(fmaxf(sp, 8.f));
}

// MLP for MROWS=32 rows starting at row0 (8 warps, 4 rows/warp).
// Lane owns 3 hidden j-pairs jp = lane + 32m; one LDS.64 of w feeds 4 rows
// (4 FFMA2). w1 streamed via cp.async double-buffered KC=16 tiles; x tile
// loaded once. Packed fma.rn.f32x2 accumulation.
__device__ __forceinline__ void mlp_block(
    const float* __restrict__ x, const float* __restrict__ w1,
    const float* __restrict__ b1, const float* __restrict__ w2,
    const float* __restrict__ b2, int row0,
    float* smem, float* __restrict__ out_tail)
{
    float* s_x = smem;                 // [MROWS][Dv]   48KB
    float* s_w = smem + MROWS * Dv;    // [2][KC][Hv]   24KB

    const int tid  = threadIdx.x;
    const int lane = tid & 31;
    const int warp = tid >> 5;
    const int rb   = warp * 4;

    // Async-load x tile (once): 3072 float4, 12 per thread.
    {
        const float4* __restrict__ xg = (const float4*)(x + (long)row0 * Dv);
        uint32_t sx = smem_u32(s_x);
#pragma unroll
        for (int i = tid; i < MROWS * Dv / 4; i += NTHR)
            CP16(sx + (uint32_t)i * 16u, xg + i);
        CP_COMMIT();
    }
    // Prefetch w tile 0.
    {
        const float4* __restrict__ wg = (const float4*)w1;
        uint32_t sw = smem_u32(s_w);
#pragma unroll
        for (int i = tid; i < KC * Hv / 4; i += NTHR)
            CP16(sw + (uint32_t)i * 16u, wg + i);
        CP_COMMIT();
    }

    uint64_t acc[4][3];
#pragma unroll
    for (int r = 0; r < 4; ++r)
#pragma unroll
        for (int m = 0; m < 3; ++m) acc[r][m] = 0ull;

    for (int t = 0; t < NTILE; ++t) {
        if (t + 1 < NTILE) {
            const float4* __restrict__ wg =
                (const float4*)(w1 + (long)(t + 1) * KC * Hv);
            uint32_t sw = smem_u32(s_w + ((t + 1) & 1) * KC * Hv);
#pragma unroll
            for (int i = tid; i < KC * Hv / 4; i += NTHR)
                CP16(sw + (uint32_t)i * 16u, wg + i);
            CP_COMMIT();
            CP_WAIT(1);           // x tile + w tile t complete
        } else {
            CP_WAIT(0);
        }
        __syncthreads();

        const float* wb = s_w + (t & 1) * KC * Hv;
#pragma unroll
        for (int k0 = 0; k0 < KC; k0 += 4) {
            float4 xa[4];
#pragma unroll
            for (int r = 0; r < 4; ++r)
                xa[r] = *(const float4*)(s_x + (rb + r) * Dv + t * KC + k0);
#pragma unroll
            for (int kk = 0; kk < 4; ++kk) {
                uint64_t xd[4];
#pragma unroll
                for (int r = 0; r < 4; ++r)
                    PACK_DUP(xd[r], __float_as_uint((&xa[r].x)[kk]));
#pragma unroll
                for (int m = 0; m < 3; ++m) {
                    uint64_t wv = *(const uint64_t*)(wb + (k0 + kk) * Hv
                                                     + 2 * (lane + 32 * m));
#pragma unroll
                    for (int r = 0; r < 4; ++r)
                        FMA_F32X2(acc[r][m], xd[r], wv, acc[r][m]);
                }
            }
        }
        __syncthreads();
    }

    // Epilogue: bias, relu, dot with w2, warp-reduce per row.
    float bz = b2[0];
    float pr[4] = {0.f, 0.f, 0.f, 0.f};
#pragma unroll
    for (int m = 0; m < 3; ++m) {
        int jp = lane + 32 * m;
        float2 bb = *(const float2*)(b1 + 2 * jp);
        float2 ww = *(const float2*)(w2 + 2 * jp);
#pragma unroll
        for (int r = 0; r < 4; ++r) {
            uint32_t lo, hi;
            UNPACK2(lo, hi, acc[r][m]);
            pr[r] += fmaxf(__uint_as_float(lo) + bb.x, 0.f) * ww.x
                   + fmaxf(__uint_as_float(hi) + bb.y, 0.f) * ww.y;
        }
    }
#pragma unroll
    for (int off = 16; off > 0; off >>= 1)
#pragma unroll
        for (int r = 0; r < 4; ++r)
            pr[r] += __shfl_xor_sync(0xffffffffu, pr[r], off);
    if (lane == 0) {
#pragma unroll
        for (int r = 0; r < 4; ++r) {
            int row = row0 + rb + r;
            float d = duration_of(pr[r] + bz);
            if (out_tail) out_tail[row] = d;
            if (row < Tv) g_dur[row] = d;
        }
    }
}

// K_A: blocks [0, NB_MLP) run the duration MLP for all batches; the rest
// zero-fill the expanded output for positions >= zstart (independent work
// that overlaps the MLP). Grid places MLP first so it starts in wave 1.
__global__ __launch_bounds__(NTHR)
void ka_kernel(const float* __restrict__ x, const float* __restrict__ w1,
               const float* __restrict__ b1, const float* __restrict__ w2,
               const float* __restrict__ b2, float* __restrict__ out,
               long TL, long tail_off, long zstart)
{
    extern __shared__ float smem[];
    if ((int)blockIdx.x < NB_MLP) {
        mlp_block(x, w1, b1, w2, b2, (int)blockIdx.x * MROWS, smem,
                  tail_off >= 0 ? out + tail_off : nullptr);
        return;
    }

    // Zero-fill: flat float4 index space over 4 slabs out[b][zstart..TL][:].
    unsigned S = (unsigned)((TL - zstart) * VD);   // f4 per slab
    unsigned total = S * Bv;
    unsigned f0 = (unsigned)(blockIdx.x - NB_MLP) * ZPB;
    if (f0 >= total) return;
    float4* __restrict__ out4 = (float4*)out;
    const float4 zf = make_float4(0.f, 0.f, 0.f, 0.f);
    const int tid = threadIdx.x;

    unsigned bA = f0 / S, bB = (min(f0 + ZPB, total) - 1) / S;
    if (bA == bB) {  // fast path: whole block inside one slab
        float4* base = out4 + ((long)bA * TL + zstart) * VD - (long)bA * S;
#pragma unroll
        for (int it = 0; it < ZPB / NTHR; ++it) {
            unsigned f = f0 + tid + it * NTHR;
            if (f < total) base[f] = zf;
        }
    } else {
#pragma unroll
        for (int it = 0; it < ZPB / NTHR; ++it) {
            unsigned f = f0 + tid + it * NTHR;
            if (f >= total) break;
            unsigned b = f / S, o = f - b * S;
            out4[((long)b * TL + zstart) * VD + o] = zf;
        }
    }
}

// K_scan: single-block inclusive scan of (int)g_dur -> g_cum, g_total.
__global__ void scan_kernel()
{
    __shared__ int s_sum[256];
    const int tid = threadIdx.x;
    int loc[8]; int s = 0;
#pragma unroll
    for (int i = 0; i < 8; ++i) { loc[i] = (int)g_dur[tid * 8 + i]; s += loc[i]; }
    s_sum[tid] = s;
    __syncthreads();
#pragma unroll
    for (int off = 1; off < 256; off <<= 1) {
        int v = (tid >= off) ? s_sum[tid - off] : 0;
        __syncthreads();
        s_sum[tid] += v;
        __syncthreads();
    }
    int run = (tid > 0) ? s_sum[tid - 1] : 0;
#pragma unroll
    for (int i = 0; i < 8; ++i) { run += loc[i]; g_cum[tid * 8 + i] = run; }
    if (tid == 255) g_total = run;
}

// K_B: gather-copy for valid positions p < g_total. Positions >= g_total
// already hold zeros from K_A (stream order makes the overwrite of
// [zstart, g_total) race-free). Warp w covers batch (w&3), positions
// [p0 + 16*(w>>2), +16): no integer division in the hot loop; each
// position row (1536 B) is written as 3 contiguous STG.128 per lane.
__global__ __launch_bounds__(NTHR)
void kb_kernel(const float* __restrict__ x, float* __restrict__ out, long TL)
{
    __shared__ int s_idx[CPP];
    __shared__ int s_ok[CPP];
    const int tid  = threadIdx.x;
    const int lane = tid & 31;
    const int warp = tid >> 5;
    long p0 = (long)blockIdx.x * CPP;
    int total = g_total;
    if (p0 >= (long)total) return;

    if (tid < CPP) {
        long p = p0 + tid;
        // searchsorted(cum, p, side="right") == upper_bound
        int lo = 0, hi = Tv;
        while (lo < hi) {
            int mid = (lo + hi) >> 1;
            if ((long)g_cum[mid] <= p) lo = mid + 1; else hi = mid;
        }
        s_idx[tid] = (lo < Tv) ? lo : (Tv - 1);
        s_ok[tid]  = (p < (long)total) && (p < TL);
    }
    __syncthreads();

    const int b  = warp & 3;
    const int h0 = (warp >> 2) * 16;
    const float4* __restrict__ xb = (const float4*)x + (long)b * Tv * VD + lane;
    float4* __restrict__ ob = (float4*)out + (long)b * TL * VD + lane;

#pragma unroll 4
    for (int i = 0; i < 16; ++i) {
        int pl = h0 + i;
        if (!s_ok[pl]) continue;
        const float4* src = xb + (long)s_idx[pl] * VD;
        float4* dst = ob + (p0 + pl) * VD;
        __stcs(dst,      __ldg(src));
        __stcs(dst + 32, __ldg(src + 32));
        __stcs(dst + 64, __ldg(src + 64));
    }
}

extern "C" void kernel_launch(void* const* d_in, const int* in_sizes, int n_in,
                              void* d_out, int out_size)
{
    const float* x  = (const float*)d_in[0];
    const float* w1 = (const float*)d_in[1];
    const float* b1 = (const float*)d_in[2];
    const float* w2 = (const float*)d_in[3];
    const float* b2 = (const float*)d_in[4];
    float* out = (float*)d_out;

    const int SMEM_DYN = (MROWS * Dv + 2 * KC * Hv) * sizeof(float); // 72KB

    static bool attr_done = false;
    if (!attr_done) {
        cudaFuncSetAttribute(ka_kernel,
            cudaFuncAttributeMaxDynamicSharedMemorySize, SMEM_DYN);
        attr_done = true;
    }

    // Output layout: expanded (Bv, TL, Dv) then duration_pred (Bv, Tv).
    long osz = (long)out_size;
    long TL, tail_off;
    if (osz % ((long)Bv * Dv) == 0) {          // no duration tail in output
        TL = osz / ((long)Bv * Dv);
        tail_off = -1;
    } else {
        TL = (osz - (long)Bv * Tv) / ((long)Bv * Dv);
        tail_off = (long)Bv * TL * Dv;
    }
    long zstart = (long)GMIN < TL ? (long)GMIN : TL;  // zeros for p >= zstart

    long zf4 = (TL - zstart) * VD * Bv;                // float4 to zero
    int nb_zero = (int)((zf4 + ZPB - 1) / ZPB);
    int nb_copy = (int)((TL + CPP - 1) / CPP);

    ka_kernel<<<NB_MLP + nb_zero, NTHR, SMEM_DYN>>>(x, w1, b1, w2, b2, out,
                                                    TL, tail_off, zstart);
    scan_kernel<<<1, 256>>>();
    kb_kernel<<<nb_copy, NTHR>>>(x, out, TL);
}

// round 7
// speedup vs baseline: 1.4872x; 1.0209x over previous
#include <cuda_runtime.h>
#include <math.h>
#include <stdint.h>

// Shapes fixed by the problem definition.
#define Bv 4
#define Tv 2048
#define Dv 384
#define Hv 192
#define VD (Dv/4)     // 96 float4 per row
#define MROWS 32      // rows per MLP block (8 warps x 4 rows)
#define NB0 (Tv/MROWS)          // 64 batch-0 MLP blocks
#define NB13 ((Bv-1)*Tv/MROWS)  // 192 MLP blocks for batches 1..3
#define KC 16         // k-tile rows (double buffered)
#define NTILE (Dv/KC) // 24
#define GMIN (8*Tv)   // guaranteed minimum total length (MIN_DUR=8)
#define CPP 32        // output positions per copy block
#define CPT 128       // positions per trailing-overflow block
#define ZPB 6144      // float4 per zero block (256 thr x 24)
#define NTHR 256

// Scratch (no allocs allowed).
__device__ float g_dur[Tv];
__device__ int   g_cum[Tv];
__device__ int   g_total;
__device__ int   g_cnt;     // batch-0 completion counter (reset by tail kernel)
__device__ int   g_ready;   // scan-done flag        (reset by tail kernel)

#define FMA_F32X2(d, a, b, c) \
    asm("fma.rn.f32x2 %0, %1, %2, %3;" : "=l"(d) : "l"(a), "l"(b), "l"(c))
#define PACK_DUP(out, v) \
    asm("mov.b64 %0, {%1, %1};" : "=l"(out) : "r"(v))
#define UNPACK2(lo, hi, in) \
    asm("mov.b64 {%0, %1}, %2;" : "=r"(lo), "=r"(hi) : "l"(in))

#define CP16(dst_u32, src_ptr) \
    asm volatile("cp.async.cg.shared.global [%0], [%1], 16;\n" :: "r"(dst_u32), "l"(src_ptr))
#define CP_COMMIT() asm volatile("cp.async.commit_group;\n")
#define CP_WAIT(n)  asm volatile("cp.async.wait_group %0;\n" :: "n"(n))

__device__ __forceinline__ uint32_t smem_u32(const void* p) {
    return (uint32_t)__cvta_generic_to_shared(p);
}

__device__ __forceinline__ float duration_of(float z) {
    // softplus -> clamp to MIN_DUR=8 -> round (nearest-even, matching jnp.round)
    float sp = (z > 20.f) ? z : log1pf(expf(z));
    return rintf(fmaxf(sp, 8.f));
}

// MLP for MROWS=32 rows starting at row0 (8 warps, 4 rows/warp).
// w1 streamed via cp.async double-buffered KC=16 tiles; x tile loaded once.
// Packed fma.rn.f32x2 accumulation. (Unchanged from R6 — proven.)
__device__ __forceinline__ void mlp_block(
    const float* __restrict__ x, const float* __restrict__ w1,
    const float* __restrict__ b1, const float* __restrict__ w2,
    const float* __restrict__ b2, int row0,
    float* smem, float* __restrict__ out_tail)
{
    float* s_x = smem;                 // [MROWS][Dv]   48KB
    float* s_w = smem + MROWS * Dv;    // [2][KC][Hv]   24KB

    const int tid  = threadIdx.x;
    const int lane = tid & 31;
    const int warp = tid >> 5;
    const int rb   = warp * 4;

    {
        const float4* __restrict__ xg = (const float4*)(x + (long)row0 * Dv);
        uint32_t sx = smem_u32(s_x);
#pragma unroll
        for (int i = tid; i < MROWS * Dv / 4; i += NTHR)
            CP16(sx + (uint32_t)i * 16u, xg + i);
        CP_COMMIT();
    }
    {
        const float4* __restrict__ wg = (const float4*)w1;
        uint32_t sw = smem_u32(s_w);
#pragma unroll
        for (int i = tid; i < KC * Hv / 4; i += NTHR)
            CP16(sw + (uint32_t)i * 16u, wg + i);
        CP_COMMIT();
    }

    uint64_t acc[4][3];
#pragma unroll
    for (int r = 0; r < 4; ++r)
#pragma unroll
        for (int m = 0; m < 3; ++m) acc[r][m] = 0ull;

    for (int t = 0; t < NTILE; ++t) {
        if (t + 1 < NTILE) {
            const float4* __restrict__ wg =
                (const float4*)(w1 + (long)(t + 1) * KC * Hv);
            uint32_t sw = smem_u32(s_w + ((t + 1) & 1) * KC * Hv);
#pragma unroll
            for (int i = tid; i < KC * Hv / 4; i += NTHR)
                CP16(sw + (uint32_t)i * 16u, wg + i);
            CP_COMMIT();
            CP_WAIT(1);
        } else {
            CP_WAIT(0);
        }
        __syncthreads();

        const float* wb = s_w + (t & 1) * KC * Hv;
#pragma unroll
        for (int k0 = 0; k0 < KC; k0 += 4) {
            float4 xa[4];
#pragma unroll
            for (int r = 0; r < 4; ++r)
                xa[r] = *(const float4*)(s_x + (rb + r) * Dv + t * KC + k0);
#pragma unroll
            for (int kk = 0; kk < 4; ++kk) {
                uint64_t xd[4];
#pragma unroll
                for (int r = 0; r < 4; ++r)
                    PACK_DUP(xd[r], __float_as_uint((&xa[r].x)[kk]));
#pragma unroll
                for (int m = 0; m < 3; ++m) {
                    uint64_t wv = *(const uint64_t*)(wb + (k0 + kk) * Hv
                                                     + 2 * (lane + 32 * m));
#pragma unroll
                    for (int r = 0; r < 4; ++r)
                        FMA_F32X2(acc[r][m], xd[r], wv, acc[r][m]);
                }
            }
        }
        __syncthreads();
    }

    float bz = b2[0];
    float pr[4] = {0.f, 0.f, 0.f, 0.f};
#pragma unroll
    for (int m = 0; m < 3; ++m) {
        int jp = lane + 32 * m;
        float2 bb = *(const float2*)(b1 + 2 * jp);
        float2 ww = *(const float2*)(w2 + 2 * jp);
#pragma unroll
        for (int r = 0; r < 4; ++r) {
            uint32_t lo, hi;
            UNPACK2(lo, hi, acc[r][m]);
            pr[r] += fmaxf(__uint_as_float(lo) + bb.x, 0.f) * ww.x
                   + fmaxf(__uint_as_float(hi) + bb.y, 0.f) * ww.y;
        }
    }
#pragma unroll
    for (int off = 16; off > 0; off >>= 1)
#pragma unroll
        for (int r = 0; r < 4; ++r)
            pr[r] += __shfl_xor_sync(0xffffffffu, pr[r], off);
    if (lane == 0) {
#pragma unroll
        for (int r = 0; r < 4; ++r) {
            int row = row0 + rb + r;
            float d = duration_of(pr[r] + bz);
            if (out_tail) out_tail[row] = d;
            if (row < Tv) g_dur[row] = d;
        }
    }
}

// Fused kernel. Grid layout (bid order = dispatch order):
//  [0, NB0)                batch-0 MLP; last finisher scans g_dur -> g_cum,
//                          g_total, then sets g_ready (fence-ordered)
//  [NB0, mlpN)             MLP for batches 1..3 (duration_pred tail only)
//  [mlpN, mlpN+nbz)        zero-fill out[b][zstart..TL][:]  (streaming stores)
//  [mlpN+nbz, ...)         gather-copy p in [0, zstart); waits on g_ready.
// Copy blocks are dispatched only after ~3072 zero blocks (~40us of store
// work), so the flag (ready ~7us in) is set long before; the spin is a
// correctness fallback, and deadlock is impossible because the flag depends
// only on bids 0..NB0-1, which dispatch and retire first.
__global__ __launch_bounds__(NTHR)
void fused_kernel(const float* __restrict__ x, const float* __restrict__ w1,
                  const float* __restrict__ b1, const float* __restrict__ w2,
                  const float* __restrict__ b2, float* __restrict__ out,
                  long TL, long tail_off, long zstart, int mlpN, int nbz)
{
    extern __shared__ float smem[];
    const int tid  = threadIdx.x;
    const int lane = tid & 31;
    const int warp = tid >> 5;
    int bid = (int)blockIdx.x;

    if (bid < mlpN) {
        int row0 = (bid < NB0) ? bid * MROWS : Tv + (bid - NB0) * MROWS;
        mlp_rows_entry:
        mlp_block(x, w1, b1, w2, b2, row0, smem,
                  tail_off >= 0 ? out + tail_off : nullptr);
        if (bid >= NB0) return;

        // Batch-0 blocks: last finisher performs the scan + publishes.
        __shared__ int s_go;
        __syncthreads();
        if (tid == 0) {
            __threadfence();
            s_go = (atomicAdd(&g_cnt, 1) == NB0 - 1);
        }
        __syncthreads();
        if (!s_go) return;
        __threadfence();
        int* s_sum = (int*)smem;
        int loc[8]; int s = 0;
#pragma unroll
        for (int i = 0; i < 8; ++i) { loc[i] = (int)g_dur[tid * 8 + i]; s += loc[i]; }
        s_sum[tid] = s;
        __syncthreads();
#pragma unroll
        for (int off = 1; off < 256; off <<= 1) {
            int v = (tid >= off) ? s_sum[tid - off] : 0;
            __syncthreads();
            s_sum[tid] += v;
            __syncthreads();
        }
        int run = (tid > 0) ? s_sum[tid - 1] : 0;
#pragma unroll
        for (int i = 0; i < 8; ++i) { run += loc[i]; g_cum[tid * 8 + i] = run; }
        if (tid == 255) g_total = run;
        __syncthreads();
        if (tid == 0) {
            __threadfence();
            atomicExch(&g_ready, 1);
        }
        return;
    }
    bid -= mlpN;
    float4* __restrict__ out4 = (float4*)out;

    if (bid < nbz) {
        // Zero-fill: flat float4 index space over Bv slabs out[b][zstart..TL][:].
        unsigned S = (unsigned)((TL - zstart) * VD);   // f4 per slab
        unsigned total = S * Bv;
        unsigned f0 = (unsigned)bid * ZPB;
        if (f0 >= total) return;
        const float4 zf = make_float4(0.f, 0.f, 0.f, 0.f);

        unsigned bA = f0 / S, bB = (min(f0 + ZPB, total) - 1) / S;
        if (bA == bB) {  // fast path: whole block inside one slab
            float4* base = out4 + ((long)bA * TL + zstart) * VD - (long)bA * S;
#pragma unroll
            for (int it = 0; it < ZPB / NTHR; ++it) {
                unsigned f = f0 + tid + it * NTHR;
                if (f < total) __stcs(base + f, zf);
            }
        } else {
#pragma unroll
            for (int it = 0; it < ZPB / NTHR; ++it) {
                unsigned f = f0 + tid + it * NTHR;
                if (f >= total) break;
                unsigned b = f / S, o = f - b * S;
                __stcs(out4 + ((long)b * TL + zstart) * VD + o, zf);
            }
        }
        return;
    }
    bid -= nbz;

    // Gather-copy for p in [0, zstart) (zstart <= g_total always, since every
    // duration >= 8). Wait for the scan's publish flag first.
    if (tid == 0) {
        while (atomicAdd(&g_ready, 0) == 0) __nanosleep(64);
    }
    __syncthreads();
    __threadfence();

    long p0 = (long)bid * CPP;
    __shared__ int s_idx[CPP];
    __shared__ int s_ok[CPP];
    if (tid < CPP) {
        long p = p0 + tid;
        // searchsorted(cum, p, side="right") == upper_bound
        int lo = 0, hi = Tv;
        while (lo < hi) {
            int mid = (lo + hi) >> 1;
            if ((long)g_cum[mid] <= p) lo = mid + 1; else hi = mid;
        }
        s_idx[tid] = (lo < Tv) ? lo : (Tv - 1);
        s_ok[tid]  = (p < zstart) && (p < TL);
    }
    __syncthreads();

    const int b  = warp & 3;
    const int h0 = (warp >> 2) * 16;
    const float4* __restrict__ xb = (const float4*)x + (long)b * Tv * VD + lane;
    float4* __restrict__ ob = out4 + (long)b * TL * VD + lane;

#pragma unroll 4
    for (int i = 0; i < 16; ++i) {
        int pl = h0 + i;
        if (!s_ok[pl]) continue;
        const float4* src = xb + (long)s_idx[pl] * VD;
        float4* dst = ob + (p0 + pl) * VD;
        __stcs(dst,      __ldg(src));
        __stcs(dst + 32, __ldg(src + 32));
        __stcs(dst + 64, __ldg(src + 64));
    }
}

// Tail kernel: resets the replay-state flags, and copies the overflow region
// [zstart, g_total) over the zeros (empty when g_total == GMIN; blocks exit
// after one load). Runs after fused_kernel, so ordering is race-free.
__global__ __launch_bounds__(NTHR)
void tail_kernel(const float* __restrict__ x, float* __restrict__ out,
                 long TL, long zstart)
{
    const int tid  = threadIdx.x;
    const int lane = tid & 31;
    const int warp = tid >> 5;
    if (blockIdx.x == 0 && tid == 0) { g_cnt = 0; g_ready = 0; }

    long p0 = zstart + (long)blockIdx.x * CPT;
    long total = (long)g_total; if (total > TL) total = TL;
    if (p0 >= total) return;

    __shared__ int s_idx[CPT];
    __shared__ int s_ok[CPT];
    for (int j = tid; j < CPT; j += NTHR) {
        long p = p0 + j;
        int lo = 0, hi = Tv;
        while (lo < hi) {
            int mid = (lo + hi) >> 1;
            if ((long)g_cum[mid] <= p) lo = mid + 1; else hi = mid;
        }
        s_idx[j] = (lo < Tv) ? lo : (Tv - 1);
        s_ok[j]  = (p < total);
    }
    __syncthreads();

    const int b  = warp & 3;
    const float4* __restrict__ xb = (const float4*)x + (long)b * Tv * VD + lane;
    float4* __restrict__ ob = (float4*)out + (long)b * TL * VD + lane;
    for (int i = warp >> 2; i < CPT; i += 2) {
        if (!s_ok[i]) continue;
        const float4* src = xb + (long)s_idx[i] * VD;
        float4* dst = ob + (p0 + i) * VD;
        __stcs(dst,      __ldg(src));
        __stcs(dst + 32, __ldg(src + 32));
        __stcs(dst + 64, __ldg(src + 64));
    }
}

extern "C" void kernel_launch(void* const* d_in, const int* in_sizes, int n_in,
                              void* d_out, int out_size)
{
    const float* x  = (const float*)d_in[0];
    const float* w1 = (const float*)d_in[1];
    const float* b1 = (const float*)d_in[2];
    const float* w2 = (const float*)d_in[3];
    const float* b2 = (const float*)d_in[4];
    float* out = (float*)d_out;

    const int SMEM_DYN = (MROWS * Dv + 2 * KC * Hv) * sizeof(float); // 72KB

    static bool attr_done = false;
    if (!attr_done) {
        cudaFuncSetAttribute(fused_kernel,
            cudaFuncAttributeMaxDynamicSharedMemorySize, SMEM_DYN);
        attr_done = true;
    }

    // Output layout: expanded (Bv, TL, Dv) then duration_pred (Bv, Tv).
    long osz = (long)out_size;
    long TL, tail_off;
    if (osz % ((long)Bv * Dv) == 0) {          // no duration tail in output
        TL = osz / ((long)Bv * Dv);
        tail_off = -1;
    } else {
        TL = (osz - (long)Bv * Tv) / ((long)Bv * Dv);
        tail_off = (long)Bv * TL * Dv;
    }
    long zstart = (long)GMIN < TL ? (long)GMIN : TL;  // zeros for p >= zstart

    long zf4 = (TL - zstart) * VD * Bv;                // float4 to zero
    int nbz  = (int)((zf4 + ZPB - 1) / ZPB);
    int nbc  = (int)((zstart + CPP - 1) / CPP);
    int mlpN = NB0 + ((tail_off >= 0) ? NB13 : 0);

    int nbt = (int)((TL - zstart + CPT - 1) / CPT);
    if (nbt < 1) nbt = 1;

    fused_kernel<<<mlpN + nbz + nbc, NTHR, SMEM_DYN>>>(x, w1, b1, w2, b2, out,
                                                       TL, tail_off, zstart,
                                                       mlpN, nbz);
    tail_kernel<<<nbt, NTHR>>>(x, out, TL, zstart);
}